// round 4
// baseline (speedup 1.0000x reference)
#include <cuda_runtime.h>
#include <cuda_bf16.h>

#define N_PTS 10000
#define DIM 64
#define EPS 0.4f
#define TILE 64
#define NT ((N_PTS + TILE - 1) / TILE)   // 157
#define ECAP (1 << 22)                    // 4M edge capacity (expect ~27K)
#define CC_ROUNDS 16

// -------- static device scratch (no allocations allowed) --------
__device__ float g_nf[N_PTS * DIM];   // normalized features
__device__ int   g_ecount;            // edge counter
__device__ int2  g_edges[ECAP];       // edge list (u < v)
__device__ int   g_lab[N_PTS];        // labels (monotone-min propagated)
__device__ int   g_pref[N_PTS];       // inclusive prefix count of roots

// -------- 1) normalize rows + init labels + reset edge counter -------------
__global__ void norm_init_kernel(const float* __restrict__ x) {
    int gtid = blockIdx.x * blockDim.x + threadIdx.x;
    if (gtid == 0) g_ecount = 0;
    int warp = gtid >> 5;
    int lane = threadIdx.x & 31;
    if (warp >= N_PTS) return;
    float a = x[warp * DIM + lane];
    float b = x[warp * DIM + 32 + lane];
    float ss = a * a + b * b;
    #pragma unroll
    for (int o = 16; o; o >>= 1) ss += __shfl_xor_sync(0xffffffffu, ss, o);
    float s = sqrtf(ss);              // IEEE sqrt + IEEE div (match reference)
    g_nf[warp * DIM + lane]      = a / s;
    g_nf[warp * DIM + 32 + lane] = b / s;
    if (lane == 0) g_lab[warp] = warp;
}

// -------- 2) tiled pairwise similarity (upper triangle) -> edge list -------
// 64x64 tile, 256 threads, 4x4 micro-tile per thread. [64][65] padding makes
// both the a-broadcast and the b-strided shared reads conflict-free.
__global__ void __launch_bounds__(256) pair_edges_kernel() {
    int bi = blockIdx.y;
    int bj = blockIdx.x;
    if (bj < bi) return;   // upper triangle only (graph is symmetric)

    __shared__ float As[TILE][DIM + 1];
    __shared__ float Bs[TILE][DIM + 1];

    int t = threadIdx.x;
    int i0 = bi * TILE;
    int j0 = bj * TILE;

    // cooperative coalesced load: consecutive t -> consecutive col
    for (int idx = t; idx < TILE * DIM; idx += 256) {
        int row = idx >> 6;
        int col = idx & 63;
        As[row][col] = (i0 + row < N_PTS) ? g_nf[(i0 + row) * DIM + col] : 0.0f;
        Bs[row][col] = (j0 + row < N_PTS) ? g_nf[(j0 + row) * DIM + col] : 0.0f;
    }
    __syncthreads();

    int ty = t >> 4;   // 0..15
    int tx = t & 15;   // 0..15

    float acc[4][4];
    #pragma unroll
    for (int r = 0; r < 4; r++)
        #pragma unroll
        for (int c = 0; c < 4; c++) acc[r][c] = 0.0f;

    #pragma unroll 8
    for (int k = 0; k < DIM; k++) {
        float a[4], b[4];
        #pragma unroll
        for (int r = 0; r < 4; r++) a[r] = As[ty + 16 * r][k];
        #pragma unroll
        for (int c = 0; c < 4; c++) b[c] = Bs[tx + 16 * c][k];
        #pragma unroll
        for (int r = 0; r < 4; r++)
            #pragma unroll
            for (int c = 0; c < 4; c++)
                acc[r][c] += a[r] * b[c];
    }

    // emit edges (sparse: mean degree ~5)
    #pragma unroll
    for (int r = 0; r < 4; r++) {
        int gi = i0 + ty + 16 * r;
        #pragma unroll
        for (int c = 0; c < 4; c++) {
            int gj = j0 + tx + 16 * c;
            if (gj > gi && gj < N_PTS && gi < N_PTS && acc[r][c] > EPS) {
                int slot = atomicAdd(&g_ecount, 1);
                if (slot < ECAP) g_edges[slot] = make_int2(gi, gj);
            }
        }
    }
}

// -------- 3a) one edge-relaxation sweep (monotone atomicMin) ---------------
__global__ void relax_kernel() {
    int m = g_ecount;
    if (m > ECAP) m = ECAP;
    for (int i = blockIdx.x * blockDim.x + threadIdx.x; i < m;
         i += gridDim.x * blockDim.x) {
        int2 e = g_edges[i];
        int lu = g_lab[e.x];
        int lv = g_lab[e.y];
        if (lu < lv)      atomicMin(&g_lab[e.y], lu);
        else if (lv < lu) atomicMin(&g_lab[e.x], lv);
    }
}

// -------- 3b) two-hop pointer jump (monotone) ------------------------------
__global__ void jump_kernel() {
    int i = blockIdx.x * blockDim.x + threadIdx.x;
    if (i >= N_PTS) return;
    int l  = g_lab[i];
    int l2 = g_lab[l];
    int l3 = g_lab[l2];
    if (l3 < l) g_lab[i] = l3;
}

// -------- 4) single-block inclusive scan of root flags ---------------------
__global__ void __launch_bounds__(1024) scan_kernel() {
    __shared__ int wsum[32];
    __shared__ int carry;
    int t = threadIdx.x;
    int lane = t & 31;
    int wid = t >> 5;
    if (t == 0) carry = 0;
    __syncthreads();

    for (int base = 0; base < N_PTS; base += 1024) {
        int idx = base + t;
        int v = (idx < N_PTS && g_lab[idx] == idx) ? 1 : 0;
        int x = v;
        #pragma unroll
        for (int o = 1; o < 32; o <<= 1) {
            int y = __shfl_up_sync(0xffffffffu, x, o);
            if (lane >= o) x += y;
        }
        if (lane == 31) wsum[wid] = x;
        __syncthreads();
        if (wid == 0) {
            int w = wsum[lane];
            #pragma unroll
            for (int o = 1; o < 32; o <<= 1) {
                int y = __shfl_up_sync(0xffffffffu, w, o);
                if (lane >= o) w += y;
            }
            wsum[lane] = w;
        }
        __syncthreads();
        int incl = x + (wid ? wsum[wid - 1] : 0) + carry;
        if (idx < N_PTS) g_pref[idx] = incl;
        __syncthreads();
        if (t == 1023) carry = incl;
        __syncthreads();
    }
}

// -------- 5) final labels (as FLOAT: harness output dtype is float32) ------
__global__ void label_kernel(float* __restrict__ out) {
    int i = blockIdx.x * blockDim.x + threadIdx.x;
    if (i >= N_PTS) return;
    out[i] = (float)(g_pref[g_lab[i]] - 1);
}

extern "C" void kernel_launch(void* const* d_in, const int* in_sizes, int n_in,
                              void* d_out, int out_size) {
    const float* x = (const float*)d_in[0];
    float* out = (float*)d_out;

    norm_init_kernel<<<(N_PTS * 32 + 255) / 256, 256>>>(x);

    dim3 grid(NT, NT);
    pair_edges_kernel<<<grid, 256>>>();

    for (int r = 0; r < CC_ROUNDS; r++) {
        relax_kernel<<<128, 256>>>();
        jump_kernel<<<(N_PTS + 255) / 256, 256>>>();
    }

    scan_kernel<<<1, 1024>>>();
    label_kernel<<<(N_PTS + 255) / 256, 256>>>(out);
}

// round 5
// speedup vs baseline: 1.2946x; 1.2946x over previous
#include <cuda_runtime.h>
#include <cuda_bf16.h>

#define N_PTS 10000
#define DIM 64
#define EPS 0.4f
#define TILE 64
#define NT ((N_PTS + TILE - 1) / TILE)   // 157
#define ECAP (1 << 22)                    // 4M edge capacity (expect ~27K)
#define WORDS ((N_PTS + 31) / 32)         // 313

// -------- static device scratch (no allocations allowed) --------
__device__ float g_nf_T[DIM * N_PTS];  // normalized features, TRANSPOSED [d][p]
__device__ int   g_ecount;             // edge counter
__device__ int2  g_edges[ECAP];        // edge list (u < v)

// -------- 1) normalize rows, write transposed (coalesced via smem) --------
// 256 threads = 8 warps; block handles 32 points; each warp does 4 points.
__global__ void __launch_bounds__(256) norm_init_kernel(const float* __restrict__ x) {
    __shared__ float sh[DIM][33];   // [d][local point], pad kills write conflicts
    if (blockIdx.x == 0 && threadIdx.x == 0) g_ecount = 0;

    int p0 = blockIdx.x * 32;
    int warp = threadIdx.x >> 5;
    int lane = threadIdx.x & 31;

    #pragma unroll
    for (int q = 0; q < 4; q++) {
        int p = p0 + warp * 4 + q;
        float a = 0.f, b = 0.f;
        if (p < N_PTS) {
            a = x[p * DIM + lane];
            b = x[p * DIM + 32 + lane];
        }
        float ss = a * a + b * b;
        #pragma unroll
        for (int o = 16; o; o >>= 1) ss += __shfl_xor_sync(0xffffffffu, ss, o);
        float s = sqrtf(ss);
        sh[lane][warp * 4 + q]      = (p < N_PTS) ? a / s : 0.f;
        sh[lane + 32][warp * 4 + q] = (p < N_PTS) ? b / s : 0.f;
    }
    __syncthreads();

    // coalesced transposed store: thread t -> (d = t>>5 + dd, p = t&31)
    int pl = threadIdx.x & 31;
    int d0 = threadIdx.x >> 5;
    if (p0 + pl < N_PTS) {
        #pragma unroll
        for (int dd = 0; dd < DIM; dd += 8)
            g_nf_T[(d0 + dd) * N_PTS + p0 + pl] = sh[d0 + dd][pl];
    }
}

// -------- 2) tiled pairwise similarity (upper triangle) -> edge list -------
// 64x64 tile, 128 threads, 8x4 micro-tile. Smem holds K-major transposed
// tiles so compute loads are LDS.128 (3 per k-step) vs 32 FFMA: FFMA-bound.
__global__ void __launch_bounds__(128) pair_edges_kernel() {
    int bi = blockIdx.y;
    int bj = blockIdx.x;
    if (bj < bi) return;   // upper triangle only (graph is symmetric)

    __shared__ float As_T[DIM][TILE];   // [k][m]
    __shared__ float Bs_T[DIM][TILE];   // [k][n]

    int t = threadIdx.x;
    int i0 = bi * TILE;
    int j0 = bj * TILE;

    // coalesced loads from transposed global: row k is contiguous in p
    #pragma unroll
    for (int it = 0; it < (DIM * TILE) / 128; it++) {
        int idx = it * 128 + t;
        int k = idx >> 6;
        int m = idx & 63;
        As_T[k][m] = (i0 + m < N_PTS) ? g_nf_T[k * N_PTS + i0 + m] : 0.0f;
        Bs_T[k][m] = (j0 + m < N_PTS) ? g_nf_T[k * N_PTS + j0 + m] : 0.0f;
    }
    __syncthreads();

    int ty = t >> 4;   // 0..7   (8 row-groups of 8)
    int tx = t & 15;   // 0..15  (16 col-groups of 4)

    float acc[8][4];
    #pragma unroll
    for (int r = 0; r < 8; r++)
        #pragma unroll
        for (int c = 0; c < 4; c++) acc[r][c] = 0.0f;

    #pragma unroll 4
    for (int k = 0; k < DIM; k++) {
        float4 a0 = *(const float4*)&As_T[k][ty * 8];
        float4 a1 = *(const float4*)&As_T[k][ty * 8 + 4];
        float4 b  = *(const float4*)&Bs_T[k][tx * 4];
        float av[8] = {a0.x, a0.y, a0.z, a0.w, a1.x, a1.y, a1.z, a1.w};
        float bv[4] = {b.x, b.y, b.z, b.w};
        #pragma unroll
        for (int r = 0; r < 8; r++)
            #pragma unroll
            for (int c = 0; c < 4; c++)
                acc[r][c] += av[r] * bv[c];
    }

    // emit edges (sparse: mean degree ~5)
    #pragma unroll
    for (int r = 0; r < 8; r++) {
        int gi = i0 + ty * 8 + r;
        #pragma unroll
        for (int c = 0; c < 4; c++) {
            int gj = j0 + tx * 4 + c;
            if (gj > gi && gj < N_PTS && gi < N_PTS && acc[r][c] > EPS) {
                int slot = atomicAdd(&g_ecount, 1);
                if (slot < ECAP) g_edges[slot] = make_int2(gi, gj);
            }
        }
    }
}

// -------- 3) fused CC + dense re-rank + float output (single block) --------
// Min-label propagation in shared memory: monotone (labels only decrease),
// fixpoint = component min index. Early exit, hard cap guarantees termination.
__global__ void __launch_bounds__(1024) cc_kernel(float* __restrict__ out) {
    __shared__ int lab[N_PTS];
    __shared__ unsigned bitmap[WORDS];
    __shared__ int wpref[WORDS];
    __shared__ int changed;

    int t = threadIdx.x;
    for (int i = t; i < N_PTS; i += 1024) lab[i] = i;
    int m = g_ecount;
    if (m > ECAP) m = ECAP;
    __syncthreads();

    for (int iter = 0; iter < 64; iter++) {
        if (t == 0) changed = 0;
        __syncthreads();

        // edge relaxation (order-independent: monotone shared atomicMin)
        for (int e = t; e < m; e += 1024) {
            int2 ed = g_edges[e];
            int a = lab[ed.x];
            int b = lab[ed.y];
            if (a < b) {
                if (atomicMin(&lab[ed.y], a) > a) changed = 1;
            } else if (b < a) {
                if (atomicMin(&lab[ed.x], b) > b) changed = 1;
            }
        }
        __syncthreads();

        // two pointer-jump rounds (monotone; 4B writes are atomic)
        #pragma unroll
        for (int j = 0; j < 2; j++) {
            for (int i = t; i < N_PTS; i += 1024) {
                int l = lab[i];
                int l2 = lab[l];
                if (l2 < l) { lab[i] = l2; changed = 1; }
            }
            __syncthreads();
        }

        int c = changed;   // writes visible after sync above
        __syncthreads();   // everyone reads before next-iter reset
        if (!c) break;     // uniform exit
    }

    // roots bitmap
    for (int w = t; w < WORDS; w += 1024) bitmap[w] = 0u;
    __syncthreads();
    for (int i = t; i < N_PTS; i += 1024)
        if (lab[i] == i) atomicOr(&bitmap[i >> 5], 1u << (i & 31));
    __syncthreads();

    // exclusive prefix of popcounts (313 words: serial is negligible)
    if (t == 0) {
        int s = 0;
        for (int w = 0; w < WORDS; w++) { wpref[w] = s; s += __popc(bitmap[w]); }
    }
    __syncthreads();

    // label(i) = rank of its component root among all roots (float output)
    for (int i = t; i < N_PTS; i += 1024) {
        int l = lab[i];
        int rank = wpref[l >> 5] + __popc(bitmap[l >> 5] & ((1u << (l & 31)) - 1u));
        out[i] = (float)rank;
    }
}

extern "C" void kernel_launch(void* const* d_in, const int* in_sizes, int n_in,
                              void* d_out, int out_size) {
    const float* x = (const float*)d_in[0];
    float* out = (float*)d_out;

    norm_init_kernel<<<(N_PTS + 31) / 32, 256>>>(x);

    dim3 grid(NT, NT);
    pair_edges_kernel<<<grid, 128>>>();

    cc_kernel<<<1, 1024>>>(out);
}

// round 6
// speedup vs baseline: 1.4523x; 1.1218x over previous
#include <cuda_runtime.h>
#include <cuda_bf16.h>

#define N_PTS 10000
#define DIM 64
#define EPS 0.4f
#define BM 128
#define NB ((N_PTS + BM - 1) / BM)       // 79
#define ECAP (1 << 22)                    // 4M edge capacity (expect ~27K)
#define SM_EDGES 32768                    // edges cached in cc smem
#define WORDS ((N_PTS + 31) / 32)         // 313

// -------- static device scratch (no allocations allowed) --------
__device__ float g_nf_T[DIM * N_PTS];  // normalized features, TRANSPOSED [d][p]
__device__ int   g_ecount;             // edge counter
__device__ int2  g_edges[ECAP];        // edge list (u < v)

// -------- 1) normalize rows, write transposed (coalesced via smem) --------
__global__ void __launch_bounds__(256) norm_init_kernel(const float* __restrict__ x) {
    __shared__ float sh[DIM][33];
    if (blockIdx.x == 0 && threadIdx.x == 0) g_ecount = 0;

    int p0 = blockIdx.x * 32;
    int warp = threadIdx.x >> 5;
    int lane = threadIdx.x & 31;

    #pragma unroll
    for (int q = 0; q < 4; q++) {
        int p = p0 + warp * 4 + q;
        float a = 0.f, b = 0.f;
        if (p < N_PTS) {
            a = x[p * DIM + lane];
            b = x[p * DIM + 32 + lane];
        }
        float ss = a * a + b * b;
        #pragma unroll
        for (int o = 16; o; o >>= 1) ss += __shfl_xor_sync(0xffffffffu, ss, o);
        float s = sqrtf(ss);
        sh[lane][warp * 4 + q]      = (p < N_PTS) ? a / s : 0.f;
        sh[lane + 32][warp * 4 + q] = (p < N_PTS) ? b / s : 0.f;
    }
    __syncthreads();

    int pl = threadIdx.x & 31;
    int d0 = threadIdx.x >> 5;
    if (p0 + pl < N_PTS) {
        #pragma unroll
        for (int dd = 0; dd < DIM; dd += 8)
            g_nf_T[(d0 + dd) * N_PTS + p0 + pl] = sh[d0 + dd][pl];
    }
}

// -------- 2) 128x128 tile pairwise similarity -> edge list -----------------
// 256 threads, 8x8 micro-tile split 4+4 at stride 64 so b-loads are 16
// contiguous float4s (conflict-free) and a-loads are 16-lane broadcasts.
// 16 smem floats per 64 FFMA = 1.0 B/FMA: at the crossbar/FFMA balance point.
__global__ void __launch_bounds__(256) pair_edges_kernel() {
    int bi = blockIdx.y;
    int bj = blockIdx.x;
    if (bj < bi) return;   // upper triangle only

    extern __shared__ float smem[];
    float* As = smem;               // [64][128] k-major
    float* Bs = smem + DIM * BM;    // [64][128]

    int t = threadIdx.x;
    int i0 = bi * BM;
    int j0 = bj * BM;

    // coalesced loads from transposed global: row k contiguous in p
    #pragma unroll
    for (int it = 0; it < (DIM * BM) / 256; it++) {
        int idx = it * 256 + t;
        int k = idx >> 7;
        int m = idx & 127;
        As[idx] = (i0 + m < N_PTS) ? g_nf_T[k * N_PTS + i0 + m] : 0.0f;
        Bs[idx] = (j0 + m < N_PTS) ? g_nf_T[k * N_PTS + j0 + m] : 0.0f;
    }
    __syncthreads();

    int ty = t >> 4;   // 0..15 -> rows ty*4..+3 and ty*4+64..+3
    int tx = t & 15;   // 0..15 -> cols tx*4..+3 and tx*4+64..+3

    float acc[8][8];
    #pragma unroll
    for (int r = 0; r < 8; r++)
        #pragma unroll
        for (int c = 0; c < 8; c++) acc[r][c] = 0.0f;

    #pragma unroll 8
    for (int k = 0; k < DIM; k++) {
        const float* ak = As + k * BM;
        const float* bk = Bs + k * BM;
        float4 a0 = *(const float4*)(ak + ty * 4);
        float4 a1 = *(const float4*)(ak + ty * 4 + 64);
        float4 b0 = *(const float4*)(bk + tx * 4);
        float4 b1 = *(const float4*)(bk + tx * 4 + 64);
        float av[8] = {a0.x, a0.y, a0.z, a0.w, a1.x, a1.y, a1.z, a1.w};
        float bv[8] = {b0.x, b0.y, b0.z, b0.w, b1.x, b1.y, b1.z, b1.w};
        #pragma unroll
        for (int r = 0; r < 8; r++)
            #pragma unroll
            for (int c = 0; c < 8; c++)
                acc[r][c] += av[r] * bv[c];
    }

    // emit edges (sparse: mean degree ~5)
    #pragma unroll
    for (int r = 0; r < 8; r++) {
        int gi = i0 + ty * 4 + (r & 3) + (r >> 2) * 64;
        #pragma unroll
        for (int c = 0; c < 8; c++) {
            int gj = j0 + tx * 4 + (c & 3) + (c >> 2) * 64;
            if (gj > gi && gj < N_PTS && gi < N_PTS && acc[r][c] > EPS) {
                int slot = atomicAdd(&g_ecount, 1);
                if (slot < ECAP) g_edges[slot] = make_int2(gi, gj);
            }
        }
    }
}

// -------- 3) fused CC + dense re-rank + float output (single block) --------
// Labels AND edges in shared memory: relax iterations never touch L2.
__global__ void __launch_bounds__(1024) cc_kernel(float* __restrict__ out) {
    extern __shared__ int dyn[];
    int* lab = dyn;               // [N_PTS]
    int* se  = dyn + N_PTS;       // [SM_EDGES] packed (u<<14 | v)
    __shared__ unsigned bitmap[WORDS];
    __shared__ int wpref[WORDS];
    __shared__ int changed;

    int t = threadIdx.x;
    for (int i = t; i < N_PTS; i += 1024) lab[i] = i;
    int m = g_ecount;
    if (m > ECAP) m = ECAP;
    int ms = m < SM_EDGES ? m : SM_EDGES;
    for (int e = t; e < ms; e += 1024) {
        int2 ed = g_edges[e];
        se[e] = (ed.x << 14) | ed.y;
    }
    __syncthreads();

    for (int iter = 0; iter < 64; iter++) {
        if (t == 0) changed = 0;
        __syncthreads();

        // smem edge relaxation (monotone atomicMin: order-independent)
        for (int e = t; e < ms; e += 1024) {
            int p = se[e];
            int u = p >> 14;
            int v = p & 16383;
            int a = lab[u];
            int b = lab[v];
            if (a < b) {
                if (atomicMin(&lab[v], a) > a) changed = 1;
            } else if (b < a) {
                if (atomicMin(&lab[u], b) > b) changed = 1;
            }
        }
        // overflow tail from global (normally empty)
        for (int e = SM_EDGES + t; e < m; e += 1024) {
            int2 ed = g_edges[e];
            int a = lab[ed.x];
            int b = lab[ed.y];
            if (a < b) {
                if (atomicMin(&lab[ed.y], a) > a) changed = 1;
            } else if (b < a) {
                if (atomicMin(&lab[ed.x], b) > b) changed = 1;
            }
        }
        __syncthreads();

        // two pointer-jump rounds (monotone)
        #pragma unroll
        for (int j = 0; j < 2; j++) {
            for (int i = t; i < N_PTS; i += 1024) {
                int l = lab[i];
                int l2 = lab[l];
                if (l2 < l) { lab[i] = l2; changed = 1; }
            }
            __syncthreads();
        }

        int c = changed;
        __syncthreads();
        if (!c) break;
    }

    // roots bitmap
    for (int w = t; w < WORDS; w += 1024) bitmap[w] = 0u;
    __syncthreads();
    for (int i = t; i < N_PTS; i += 1024)
        if (lab[i] == i) atomicOr(&bitmap[i >> 5], 1u << (i & 31));
    __syncthreads();

    if (t == 0) {
        int s = 0;
        for (int w = 0; w < WORDS; w++) { wpref[w] = s; s += __popc(bitmap[w]); }
    }
    __syncthreads();

    for (int i = t; i < N_PTS; i += 1024) {
        int l = lab[i];
        int rank = wpref[l >> 5] + __popc(bitmap[l >> 5] & ((1u << (l & 31)) - 1u));
        out[i] = (float)rank;
    }
}

extern "C" void kernel_launch(void* const* d_in, const int* in_sizes, int n_in,
                              void* d_out, int out_size) {
    const float* x = (const float*)d_in[0];
    float* out = (float*)d_out;

    const int pair_smem = 2 * DIM * BM * sizeof(float);            // 64 KB
    const int cc_smem   = (N_PTS + SM_EDGES) * sizeof(int);        // ~167 KB
    cudaFuncSetAttribute(pair_edges_kernel,
                         cudaFuncAttributeMaxDynamicSharedMemorySize, pair_smem);
    cudaFuncSetAttribute(cc_kernel,
                         cudaFuncAttributeMaxDynamicSharedMemorySize, cc_smem);

    norm_init_kernel<<<(N_PTS + 31) / 32, 256>>>(x);

    dim3 grid(NB, NB);
    pair_edges_kernel<<<grid, 256, pair_smem>>>();

    cc_kernel<<<1, 1024, cc_smem>>>(out);
}

// round 7
// speedup vs baseline: 1.5704x; 1.0813x over previous
#include <cuda_runtime.h>
#include <cuda_bf16.h>

#define N_PTS 10000
#define DIM 64
#define EPS 0.4f
#define BM 128
#define NB ((N_PTS + BM - 1) / BM)       // 79
#define ECAP (1 << 22)                    // 4M edge capacity (expect ~27K)
#define SM_EDGES 32768                    // edges cached in cc smem
#define WORDS ((N_PTS + 31) / 32)         // 313

// -------- static device scratch (no allocations allowed) --------
__device__ float g_nf_T[DIM * N_PTS];  // normalized features, TRANSPOSED [d][p]
__device__ int   g_ecount;             // edge counter
__device__ int2  g_edges[ECAP];        // edge list (u < v)

// -------- packed f32x2 helpers (sm_100a: FFMA2 = 2x FMA throughput) --------
__device__ __forceinline__ unsigned long long pack2(float lo, float hi) {
    unsigned long long r;
    asm("mov.b64 %0, {%1, %2};" : "=l"(r) : "f"(lo), "f"(hi));
    return r;
}
__device__ __forceinline__ void unpack2(unsigned long long p, float& lo, float& hi) {
    asm("mov.b64 {%0, %1}, %2;" : "=f"(lo), "=f"(hi) : "l"(p));
}
__device__ __forceinline__ void fma2(unsigned long long& d,
                                     unsigned long long a,
                                     unsigned long long b) {
    // two independent IEEE fma.rn.f32 lanes -> bitwise == scalar accumulation
    asm("fma.rn.f32x2 %0, %1, %2, %3;" : "=l"(d) : "l"(a), "l"(b), "l"(d));
}

// -------- 1) normalize rows, write transposed (coalesced via smem) --------
__global__ void __launch_bounds__(256) norm_init_kernel(const float* __restrict__ x) {
    __shared__ float sh[DIM][33];
    if (blockIdx.x == 0 && threadIdx.x == 0) g_ecount = 0;

    int p0 = blockIdx.x * 32;
    int warp = threadIdx.x >> 5;
    int lane = threadIdx.x & 31;

    #pragma unroll
    for (int q = 0; q < 4; q++) {
        int p = p0 + warp * 4 + q;
        float a = 0.f, b = 0.f;
        if (p < N_PTS) {
            a = x[p * DIM + lane];
            b = x[p * DIM + 32 + lane];
        }
        float ss = a * a + b * b;
        #pragma unroll
        for (int o = 16; o; o >>= 1) ss += __shfl_xor_sync(0xffffffffu, ss, o);
        float s = sqrtf(ss);
        sh[lane][warp * 4 + q]      = (p < N_PTS) ? a / s : 0.f;
        sh[lane + 32][warp * 4 + q] = (p < N_PTS) ? b / s : 0.f;
    }
    __syncthreads();

    int pl = threadIdx.x & 31;
    int d0 = threadIdx.x >> 5;
    if (p0 + pl < N_PTS) {
        #pragma unroll
        for (int dd = 0; dd < DIM; dd += 8)
            g_nf_T[(d0 + dd) * N_PTS + p0 + pl] = sh[d0 + dd][pl];
    }
}

// -------- 2) 128x128 tile pairwise similarity -> edge list (FFMA2) ---------
// 256 threads, 8x8 micro-tile (4+4 rows/cols at stride 64). Accumulators are
// 32 packed f32x2 pairs; 32 FFMA2 per k-step vs 4 LDS.128: FFMA2-pipe-bound.
__global__ void __launch_bounds__(256) pair_edges_kernel() {
    int bi = blockIdx.y;
    int bj = blockIdx.x;
    if (bj < bi) return;   // upper triangle only

    extern __shared__ float smem[];
    float* As = smem;               // [64][128] k-major
    float* Bs = smem + DIM * BM;    // [64][128]

    int t = threadIdx.x;
    int i0 = bi * BM;
    int j0 = bj * BM;

    #pragma unroll
    for (int it = 0; it < (DIM * BM) / 256; it++) {
        int idx = it * 256 + t;
        int k = idx >> 7;
        int m = idx & 127;
        As[idx] = (i0 + m < N_PTS) ? g_nf_T[k * N_PTS + i0 + m] : 0.0f;
        Bs[idx] = (j0 + m < N_PTS) ? g_nf_T[k * N_PTS + j0 + m] : 0.0f;
    }
    __syncthreads();

    int ty = t >> 4;   // 0..15 -> rows ty*4..+3 and ty*4+64..+3
    int tx = t & 15;   // 0..15 -> cols tx*4..+3 and tx*4+64..+3

    // acc2[r][cp]: row r (0..7), column-pair cp (cols 2cp, 2cp+1 of the 8)
    unsigned long long acc2[8][4];
    #pragma unroll
    for (int r = 0; r < 8; r++)
        #pragma unroll
        for (int c = 0; c < 4; c++) acc2[r][c] = 0ull;

    #pragma unroll 8
    for (int k = 0; k < DIM; k++) {
        const float* ak = As + k * BM;
        const float* bk = Bs + k * BM;
        float4 a0 = *(const float4*)(ak + ty * 4);
        float4 a1 = *(const float4*)(ak + ty * 4 + 64);
        float4 b0 = *(const float4*)(bk + tx * 4);
        float4 b1 = *(const float4*)(bk + tx * 4 + 64);

        unsigned long long bp[4] = {
            pack2(b0.x, b0.y), pack2(b0.z, b0.w),
            pack2(b1.x, b1.y), pack2(b1.z, b1.w)
        };
        float av[8] = {a0.x, a0.y, a0.z, a0.w, a1.x, a1.y, a1.z, a1.w};
        #pragma unroll
        for (int r = 0; r < 8; r++) {
            unsigned long long ad = pack2(av[r], av[r]);
            #pragma unroll
            for (int c = 0; c < 4; c++)
                fma2(acc2[r][c], ad, bp[c]);
        }
    }

    // emit edges (sparse: mean degree ~5)
    #pragma unroll
    for (int r = 0; r < 8; r++) {
        int gi = i0 + ty * 4 + (r & 3) + (r >> 2) * 64;
        #pragma unroll
        for (int cp = 0; cp < 4; cp++) {
            float v0, v1;
            unpack2(acc2[r][cp], v0, v1);
            int cbase = tx * 4 + ((cp & 1) * 2) + ((cp >> 1) * 64);
            int gj0 = j0 + cbase;
            if (gj0 > gi && gj0 < N_PTS && gi < N_PTS && v0 > EPS) {
                int slot = atomicAdd(&g_ecount, 1);
                if (slot < ECAP) g_edges[slot] = make_int2(gi, gj0);
            }
            int gj1 = gj0 + 1;
            if (gj1 > gi && gj1 < N_PTS && gi < N_PTS && v1 > EPS) {
                int slot = atomicAdd(&g_ecount, 1);
                if (slot < ECAP) g_edges[slot] = make_int2(gi, gj1);
            }
        }
    }
}

// -------- 3) fused CC + dense re-rank + float output (single block) --------
__global__ void __launch_bounds__(1024) cc_kernel(float* __restrict__ out) {
    extern __shared__ int dyn[];
    int* lab = dyn;               // [N_PTS]
    int* se  = dyn + N_PTS;       // [SM_EDGES] packed (u<<14 | v)
    __shared__ unsigned bitmap[WORDS];
    __shared__ int wpref[WORDS];
    __shared__ int changed;

    int t = threadIdx.x;
    for (int i = t; i < N_PTS; i += 1024) lab[i] = i;
    int m = g_ecount;
    if (m > ECAP) m = ECAP;
    int ms = m < SM_EDGES ? m : SM_EDGES;
    for (int e = t; e < ms; e += 1024) {
        int2 ed = g_edges[e];
        se[e] = (ed.x << 14) | ed.y;
    }
    __syncthreads();

    for (int iter = 0; iter < 64; iter++) {
        if (t == 0) changed = 0;
        __syncthreads();

        for (int e = t; e < ms; e += 1024) {
            int p = se[e];
            int u = p >> 14;
            int v = p & 16383;
            int a = lab[u];
            int b = lab[v];
            if (a < b) {
                if (atomicMin(&lab[v], a) > a) changed = 1;
            } else if (b < a) {
                if (atomicMin(&lab[u], b) > b) changed = 1;
            }
        }
        for (int e = SM_EDGES + t; e < m; e += 1024) {   // overflow tail
            int2 ed = g_edges[e];
            int a = lab[ed.x];
            int b = lab[ed.y];
            if (a < b) {
                if (atomicMin(&lab[ed.y], a) > a) changed = 1;
            } else if (b < a) {
                if (atomicMin(&lab[ed.x], b) > b) changed = 1;
            }
        }
        __syncthreads();

        #pragma unroll
        for (int j = 0; j < 2; j++) {
            for (int i = t; i < N_PTS; i += 1024) {
                int l = lab[i];
                int l2 = lab[l];
                if (l2 < l) { lab[i] = l2; changed = 1; }
            }
            __syncthreads();
        }

        int c = changed;
        __syncthreads();
        if (!c) break;
    }

    for (int w = t; w < WORDS; w += 1024) bitmap[w] = 0u;
    __syncthreads();
    for (int i = t; i < N_PTS; i += 1024)
        if (lab[i] == i) atomicOr(&bitmap[i >> 5], 1u << (i & 31));
    __syncthreads();

    if (t == 0) {
        int s = 0;
        for (int w = 0; w < WORDS; w++) { wpref[w] = s; s += __popc(bitmap[w]); }
    }
    __syncthreads();

    for (int i = t; i < N_PTS; i += 1024) {
        int l = lab[i];
        int rank = wpref[l >> 5] + __popc(bitmap[l >> 5] & ((1u << (l & 31)) - 1u));
        out[i] = (float)rank;
    }
}

extern "C" void kernel_launch(void* const* d_in, const int* in_sizes, int n_in,
                              void* d_out, int out_size) {
    const float* x = (const float*)d_in[0];
    float* out = (float*)d_out;

    const int pair_smem = 2 * DIM * BM * sizeof(float);            // 64 KB
    const int cc_smem   = (N_PTS + SM_EDGES) * sizeof(int);        // ~167 KB
    cudaFuncSetAttribute(pair_edges_kernel,
                         cudaFuncAttributeMaxDynamicSharedMemorySize, pair_smem);
    cudaFuncSetAttribute(cc_kernel,
                         cudaFuncAttributeMaxDynamicSharedMemorySize, cc_smem);

    norm_init_kernel<<<(N_PTS + 31) / 32, 256>>>(x);

    dim3 grid(NB, NB);
    pair_edges_kernel<<<grid, 256, pair_smem>>>();

    cc_kernel<<<1, 1024, cc_smem>>>(out);
}